// round 6
// baseline (speedup 1.0000x reference)
#include <cuda_runtime.h>
#include <math.h>

// Problem constants: B=2, S=2048, C=64, F=64, K=3
#define Bn   2
#define Sn   2048
#define Cn   64
#define Fn   64
#define Kt   3
#define TS   16               // output s-rows per block
#define RMAX 32               // D-window rows computed per block
#define Mtot (Bn * Sn)        // 4096

typedef unsigned long long ull;

// ---- packed f32x2 helpers (Blackwell 2x fp32 FMA path) ----
__device__ __forceinline__ ull pack2(float lo, float hi) {
    ull r; asm("mov.b64 %0, {%1,%2};" : "=l"(r) : "f"(lo), "f"(hi)); return r;
}
__device__ __forceinline__ void fma2(ull& d, ull a, ull b) {
    asm("fma.rn.f32x2 %0, %1, %2, %0;" : "+l"(d) : "l"(a), "l"(b));
}
__device__ __forceinline__ float2 unpack2(ull v) {
    float2 f; asm("mov.b64 {%0,%1}, %2;" : "=f"(f.x), "=f"(f.y) : "l"(v)); return f;
}

// Precomputed once per launch by prep kernel
__device__ float g_w[Fn];
__device__ int   g_I[Fn];
__device__ int   g_Imin, g_Imax, g_dil;
// Pre-transposed weights: g_wt[(h*64 + c)*96 + k*32 + fr] = kernel[h*32+fr][c][k]
__device__ float g_wt[2 * Cn * 96];

__global__ __launch_bounds__(256) void ddc_prep(
    const float* __restrict__ kw, const float* __restrict__ ow,
    const void* __restrict__ dilp)
{
    __shared__ int sI[Fn];
    const int tid = threadIdx.x;

    int d = *(const int*)dilp;                                  // int32/int64 LE
    if (d < 1 || d > 65536) d = (int)(*(const float*)dilp);     // float scalar
    if (tid == 0) g_dil = d;

    if (tid < Fn) {
        float mo  = 0.5f * (float)Sn / (float)(d * Kt);
        float off = -mo / (1.0f + expf(-ow[tid]));              // -sigmoid*max_off
        float fl  = floorf(off);
        int   I   = (int)fl;
        g_I[tid] = I; sI[tid] = I;
        g_w[tid] = off - fl;
    }
    __syncthreads();
    if (tid == 0) {
        int mn = sI[0], mx = sI[0];
        #pragma unroll
        for (int i = 1; i < Fn; i++) { mn = min(mn, sI[i]); mx = max(mx, sI[i]); }
        g_Imin = mn; g_Imax = mx;
    }
    // Transpose weights (12288 elements), coalesced reads.
    for (int idx = tid; idx < Fn * Cn * Kt; idx += 256) {
        int fg  = idx / (Cn * Kt);
        int rem = idx - fg * (Cn * Kt);
        int c = rem / Kt, k = rem - c * Kt;
        int h = fg >> 5, fr = fg & 31;
        g_wt[(h * Cn + c) * 96 + k * 32 + fr] = kw[idx];
    }
}

// Fused: grid (256, 2), 128 threads. Block = 16 s-rows x 32 features (half h).
// Computes the 32-row x 96-col D window in registers (f32x2), dumps to smem,
// gathers + lerps, coalesced store.
__global__ __launch_bounds__(128) void ddc_fused(
    const float* __restrict__ x,   // (B,S,C)
    const float* __restrict__ kw,  // (F,C,K)  (fallback path only)
    float*       __restrict__ out) // (B,S,F)
{
    __shared__ __align__(16) float xs[Cn * 34];   // x window, transposed, even stride
    __shared__ __align__(16) float ws[Cn * 96];   // weights; reused as D after MMA
    __shared__ float s_w[32];
    __shared__ int   s_I[32];

    const int tid = threadIdx.x;
    const int h   = blockIdx.y;
    const int rq0 = blockIdx.x * TS;
    const int b   = rq0 >> 11;
    const int s0  = rq0 & (Sn - 1);

    const int dil  = g_dil;
    const int Imin = g_Imin, Imax = g_Imax;
    if (tid < 32) { s_w[tid] = g_w[h * 32 + tid]; s_I[tid] = g_I[h * 32 + tid]; }

    int lo = s0 + Imin - (Kt - 1) * dil; if (lo < 0) lo = 0;
    int hi = s0 + TS - 1 + Imax + 1;     if (hi > Sn - 1) hi = Sn - 1;
    const bool ok = (hi - lo + 1) <= RMAX;    // uniform across block

    const int fr = tid & 31;
    const int sl = tid >> 5;

    if (ok) {
        // Stage x window transposed: 32 rows x 64 c (coalesced 128B global reads).
        #pragma unroll
        for (int it = 0; it < (RMAX * Cn) / 128; it++) {
            int idx = tid + it * 128;
            int r = idx >> 6, c = idx & 63;
            int gr = lo + r; if (gr > Sn - 1) gr = Sn - 1;
            xs[c * 34 + r] = x[(b * Sn + gr) * Cn + c];
        }
        // Stage weights: straight float4 copy from pre-transposed global.
        {
            const float4* src = (const float4*)(g_wt + h * (Cn * 96));
            float4*       dst = (float4*)ws;
            #pragma unroll
            for (int it = 0; it < (Cn * 96 / 4) / 128; it += 1)
                dst[tid + it * 128] = src[tid + it * 128];
        }
        __syncthreads();

        // MMA: thread tile = 8 rows (4 f32x2 pairs) x 3 cols.
        const int tx = fr;          // col lane: n = tx + 32j
        const int ty = sl;          // 0..3: pair p = ty + 4*i
        ull acc[4][3];
        #pragma unroll
        for (int i = 0; i < 4; i++)
            #pragma unroll
            for (int j = 0; j < 3; j++) acc[i][j] = 0ull;

        #pragma unroll 16
        for (int c = 0; c < Cn; c++) {
            ull xv[4];
            #pragma unroll
            for (int i = 0; i < 4; i++) {
                float2 p = *(const float2*)(xs + c * 34 + 2 * (ty + 4 * i)); // LDS.64 bcast
                xv[i] = pack2(p.x, p.y);
            }
            #pragma unroll
            for (int j = 0; j < 3; j++) {
                float wsc = ws[c * 96 + tx + 32 * j];   // conflict-free
                ull wv = pack2(wsc, wsc);
                #pragma unroll
                for (int i = 0; i < 4; i++) fma2(acc[i][j], xv[i], wv);
            }
        }
        __syncthreads();   // all ws reads done before overwrite

        // Dump D (32 x 96) into ws region.
        float* D = ws;
        #pragma unroll
        for (int i = 0; i < 4; i++) {
            int p = ty + 4 * i;
            #pragma unroll
            for (int j = 0; j < 3; j++) {
                float2 v = unpack2(acc[i][j]);
                D[(2 * p)     * 96 + tx + 32 * j] = v.x;
                D[(2 * p + 1) * 96 + tx + 32 * j] = v.y;
            }
        }
        __syncthreads();

        // Gather + lerp; coalesced 128B stores per warp.
        const float w = s_w[fr];
        const int   I = s_I[fr];
        #pragma unroll
        for (int jj = 0; jj < 4; jj++) {
            int s = s0 + sl * 4 + jj;
            float y = 0.0f;
            #pragma unroll
            for (int k = 0; k < Kt; k++) {
                int i0  = s - k * dil + I;
                int i0c = min(max(i0,     0), Sn - 1);
                int i1c = min(max(i0 + 1, 0), Sn - 1);
                float d0 = D[(i0c - lo) * 96 + k * 32 + fr];
                float d1 = D[(i1c - lo) * 96 + k * 32 + fr];
                y += d0 + w * (d1 - d0);
            }
            out[(rq0 + sl * 4 + jj) * Fn + h * 32 + fr] = y;
        }
    } else {
        // Correct fallback (pathological offset spread; never triggers here).
        __syncthreads();
        const float w = s_w[fr];
        const int   I = s_I[fr];
        const int   f = h * 32 + fr;
        for (int jj = 0; jj < 4; jj++) {
            int s = s0 + sl * 4 + jj;
            float y = 0.0f;
            for (int k = 0; k < Kt; k++) {
                int i0  = s - k * dil + I;
                int i0c = min(max(i0,     0), Sn - 1);
                int i1c = min(max(i0 + 1, 0), Sn - 1);
                float a0 = 0.0f, a1 = 0.0f;
                for (int c = 0; c < Cn; c++) {
                    float kk = kw[f * (Cn * Kt) + c * Kt + k];
                    a0 += x[(b * Sn + i0c) * Cn + c] * kk;
                    a1 += x[(b * Sn + i1c) * Cn + c] * kk;
                }
                y += a0 + w * (a1 - a0);
            }
            out[(rq0 + sl * 4 + jj) * Fn + f] = y;
        }
    }
}

extern "C" void kernel_launch(void* const* d_in, const int* in_sizes, int n_in,
                              void* d_out, int out_size)
{
    const float* x   = (const float*)d_in[0];   // (B,S,C) f32
    const float* kw  = (const float*)d_in[1];   // (F,C,K) f32
    const float* ow  = (const float*)d_in[2];   // (F,)    f32
    const void*  dil = d_in[3];                 // scalar dilation_rate

    ddc_prep<<<1, 256>>>(kw, ow, dil);
    dim3 grid(Mtot / TS, 2);
    ddc_fused<<<grid, 128>>>(x, kw, (float*)d_out);
}